// round 5
// baseline (speedup 1.0000x reference)
#include <cuda_runtime.h>
#include <cstdint>
#include <math.h>

// Problem constants
#define NB    8192          // batch
#define NT    64            // time
#define NF    64            // features
#define CONV  20
#define WIN   30
#define BEGIN 15            // NT - (CONV + WIN - 1)
#define ROW0  34            // BEGIN + CONV - 1  (row of "last" for w=0)
#define OUTROW 320
#define OUTB  (WIN * OUTROW)  // 9600 floats per batch row

// ============================================================================
// Stats kernel: one thread per (b, e). Sliding S1/S2 + direct max/min over a
// 20-element register ring buffer. Coalesced loads/stores (lanes = e).
// ============================================================================
__global__ __launch_bounds__(256) void stats_kernel(const float* __restrict__ x,
                                                    float* __restrict__ out) {
    int tid = threadIdx.x;
    int e = tid & 63;
    int b = blockIdx.x * 4 + (tid >> 6);

    const float* p = x + (size_t)b * (NT * NF) + BEGIN * NF + e;
    float* ob = out + (size_t)b * OUTB + e;

    float buf[20];
    float S1 = 0.f, S2 = 0.f;
#pragma unroll
    for (int i = 0; i < 20; i++) {
        float t = p[i * NF];
        buf[i] = t;
        S1 += t;
        S2 = fmaf(t, t, S2);
    }
    // window 0
    {
        float mx = buf[0], mn = buf[0];
#pragma unroll
        for (int i = 1; i < 20; i++) { mx = fmaxf(mx, buf[i]); mn = fminf(mn, buf[i]); }
        float mean = S1 * 0.05f;
        float var = fmaf(-S1, mean, S2) * (1.0f / 19.0f);
        float sd = sqrtf(fmaxf(var, 0.f));
        ob[0] = mean; ob[64] = sd; ob[192] = mx; ob[256] = mn;
    }
#pragma unroll
    for (int w = 1; w < WIN; w++) {
        int s = (w - 1) % 20;            // slot being replaced (oldest)
        float vo = buf[s];
        float vn = p[(w + 19) * NF];
        S1 += vn - vo;
        S2 = S2 + fmaf(vn, vn, -vo * vo);
        buf[s] = vn;

        float mx = buf[0], mn = buf[0];
#pragma unroll
        for (int i = 1; i < 20; i++) { mx = fmaxf(mx, buf[i]); mn = fminf(mn, buf[i]); }
        float mean = S1 * 0.05f;
        float var = fmaf(-S1, mean, S2) * (1.0f / 19.0f);
        float sd = sqrtf(fmaxf(var, 0.f));
        float* o = ob + w * OUTROW;
        o[0] = mean; o[64] = sd; o[192] = mx; o[256] = mn;
    }
}

// ============================================================================
// Rank kernel: one block per (w, e-octet). For each of the 8 columns:
// density-adapted exact-monotone bucketing (~7800 buckets over 8192 slots),
// smem histogram -> block exclusive scan -> scatter (key32 + idx16) ->
// exact stable rank by within-bucket comparison. Ranks staged as uint16,
// written out coalesced as float4 pairs at the end.
//
// Descending key: dkey = ~monotone_ascending(v). rank[b] =
//   #{dkey' < dkey} + #{dkey'==dkey && idx' < b}   == argsort(argsort(-v))[b].
// ============================================================================
#define HBINS 8192
#define RANK_SMEM (HBINS*4 /*hist*/ + HBINS*4 /*skey*/ + NB*2 /*sidx*/ \
                   + 8*NB*2 /*stage*/ + 256*4 /*cellBase*/ + 256*4 /*cellShift*/ + 32*4 /*warpsum*/)

__global__ __launch_bounds__(1024, 1) void rank_kernel(const float* __restrict__ x,
                                                       float* __restrict__ out) {
    extern __shared__ uint8_t sm[];
    uint32_t* hist      = (uint32_t*)sm;                 // 8192 u32
    uint32_t* skey      = hist + HBINS;                  // 8192 u32
    uint16_t* sidx      = (uint16_t*)(skey + HBINS);     // 8192 u16
    uint16_t* stage     = sidx + NB;                     // 8 * 8192 u16
    uint32_t* cellBase  = (uint32_t*)(stage + 8 * NB);   // 256 u32
    uint32_t* cellShift = cellBase + 256;                // 256 u32
    uint32_t* warpsum   = cellShift + 256;               // 32 u32

    int tid = threadIdx.x;
    int lane = tid & 31, warp = tid >> 5;
    int w = blockIdx.x;
    int e0 = blockIdx.y * 8;

    // Build bucket tables (tuned for N(0,1); exactly monotone by construction).
    if (tid < 256) {
        int p = (tid >= 128) ? (tid - 128) : (127 - tid);   // = exp>>1 of |v|
        int sh;
        if      (p == 63)              sh = 13;  // |v| in [0.5, 2)   -> 2048 bins
        else if (p == 62)              sh = 14;  // [0.125, 0.5)      -> 1024
        else if (p == 64 || p == 61)   sh = 16;  // [2,8) / [1/32,1/8)->  256
        else if (p == 60)              sh = 17;  //                   ->  128
        else if (p == 59)              sh = 18;  //                   ->   64
        else                           sh = 24;  // tails / tiny      ->    1
        cellShift[tid] = (uint32_t)sh;
        hist[tid] = 1u << (24 - sh);             // cell size (temp in hist)
    }
    __syncthreads();
    if (tid == 0) {
        uint32_t acc = 0;
        for (int i = 0; i < 256; i++) { uint32_t s = hist[i]; cellBase[i] = acc; acc += s; }
        // acc == 7796 <= HBINS
    }
    __syncthreads();

    const float* xr = x + (size_t)(ROW0 + w) * NF;

    for (int col = 0; col < 8; col++) {
        int e = e0 + col;

        // zero histogram
#pragma unroll
        for (int i = 0; i < 8; i++) hist[tid + i * 1024] = 0;
        __syncthreads();

        // load keys, bucket, histogram
        uint32_t k[8];
        int bkt[8];
#pragma unroll
        for (int j = 0; j < 8; j++) {
            int b = tid + (j << 10);
            float v = __ldg(&xr[(size_t)b * (NT * NF) + e]);
            uint32_t u = __float_as_uint(v);
            uint32_t m = (u & 0x80000000u) ? ~u : (u | 0x80000000u); // ascending
            uint32_t dk = ~m;                                        // descending
            uint32_t j8 = dk >> 24;
            int bb = (int)(cellBase[j8] + ((dk & 0x00FFFFFFu) >> cellShift[j8]));
            k[j] = dk; bkt[j] = bb;
            atomicAdd(&hist[bb], 1u);
        }
        __syncthreads();

        // in-place exclusive scan of hist[0..8191]
        {
            uint32_t sum = 0;
#pragma unroll
            for (int i = 0; i < 8; i++) sum += hist[tid * 8 + i];
            uint32_t inc = sum;
#pragma unroll
            for (int o = 1; o < 32; o <<= 1) {
                uint32_t n = __shfl_up_sync(0xffffffffu, inc, o);
                if (lane >= o) inc += n;
            }
            if (lane == 31) warpsum[warp] = inc;
            __syncthreads();
            if (warp == 0) {
                uint32_t v = warpsum[lane];
                uint32_t wi = v;
#pragma unroll
                for (int o = 1; o < 32; o <<= 1) {
                    uint32_t n = __shfl_up_sync(0xffffffffu, wi, o);
                    if (lane >= o) wi += n;
                }
                warpsum[lane] = wi - v;   // exclusive warp base
            }
            __syncthreads();
            uint32_t base = warpsum[warp] + (inc - sum);
#pragma unroll
            for (int i = 0; i < 8; i++) {
                uint32_t v = hist[tid * 8 + i];
                hist[tid * 8 + i] = base;
                base += v;
            }
        }
        __syncthreads();

        // scatter (key, idx) by bucket; hist becomes inclusive prefix
#pragma unroll
        for (int j = 0; j < 8; j++) {
            uint32_t pos = atomicAdd(&hist[bkt[j]], 1u);
            skey[pos] = k[j];
            sidx[pos] = (uint16_t)(tid + (j << 10));
        }
        __syncthreads();

        // exact stable rank within bucket
#pragma unroll
        for (int j = 0; j < 8; j++) {
            uint32_t myk = k[j];
            int bb = bkt[j];
            int myb = tid + (j << 10);
            uint32_t start = bb ? hist[bb - 1] : 0u;
            uint32_t end = hist[bb];
            uint32_t r = start;
            for (uint32_t q = start; q < end; q++) {
                uint32_t kk = skey[q];
                r += (kk < myk) || (kk == myk && (int)sidx[q] < myb);
            }
            stage[col * NB + myb] = (uint16_t)r;
        }
        __syncthreads();
    }

    // coalesced write: 8 ranks per b -> two float4 stores
    const float inv = 1.0f / 8192.0f;
    float* o0 = out + (size_t)w * OUTROW + 128 + e0;
#pragma unroll
    for (int j = 0; j < 8; j++) {
        int b = tid + (j << 10);
        float4 r0, r1;
        r0.x = stage[0 * NB + b] * inv; r0.y = stage[1 * NB + b] * inv;
        r0.z = stage[2 * NB + b] * inv; r0.w = stage[3 * NB + b] * inv;
        r1.x = stage[4 * NB + b] * inv; r1.y = stage[5 * NB + b] * inv;
        r1.z = stage[6 * NB + b] * inv; r1.w = stage[7 * NB + b] * inv;
        float* dst = o0 + (size_t)b * OUTB;
        *(float4*)dst = r0;
        *(float4*)(dst + 4) = r1;
    }
}

// ============================================================================
extern "C" void kernel_launch(void* const* d_in, const int* in_sizes, int n_in,
                              void* d_out, int out_size) {
    const float* x = (const float*)d_in[0];
    float* out = (float*)d_out;
    (void)in_sizes; (void)n_in; (void)out_size;

    cudaFuncSetAttribute(rank_kernel, cudaFuncAttributeMaxDynamicSharedMemorySize,
                         RANK_SMEM);

    // rank: grid (w=30, e-octets=8), 1024 threads, ~210 KB smem
    rank_kernel<<<dim3(WIN, 8), 1024, RANK_SMEM>>>(x, out);
    // stats: 2048 blocks x 256 threads (4 batches per block, thread per (b,e))
    stats_kernel<<<NB / 4, 256>>>(x, out);
}